// round 1
// baseline (speedup 1.0000x reference)
#include <cuda_runtime.h>
#include <math.h>

// Problem constants
#define NB   4
#define CI   64        // I
#define CC   256       // C
#define GG   8         // groups
#define CG   32        // C/G
#define KK   9
#define HH   48
#define WW   48
#define HW   (HH*WW)   // 2304
#define HD   40
#define WD   40
#define DD   (HD*WD)   // 1600
#define C2   (2*CC)    // 512
#define CPG  64        // 2C/G: conv input channels per group
#define STRIDE_GATE (NB*CC*HW)

// Scratch (static device globals; allocation-free rule)
__device__ float g_xh[NB*C2*HW];       // interleaved [N][G][2][Cg][H][W]
__device__ float g_q [NB*CC*HW];
__device__ float g_k [NB*CC*DD];
__device__ float g_v [NB*CC*DD];
__device__ float g_a [NB*CC*HW];
__device__ float g_gate[4*STRIDE_GATE];

// ---------------------------------------------------------------------------
// Kernel 1: x = Wx*inp + Wxg*h  (1x1 convs), write interleaved xh (x and h)
// grid (72, 4), block 256 (thread = out channel)
// ---------------------------------------------------------------------------
__global__ __launch_bounds__(256) void proj_kernel(
    const float* __restrict__ inp, const float* __restrict__ h,
    const float* __restrict__ Wx,  const float* __restrict__ Wxg)
{
    __shared__ float s_in[CI][32];
    __shared__ float s_h [CC][32];
    const int n  = blockIdx.y;
    const int p0 = blockIdx.x * 32;
    const int t  = threadIdx.x;

    for (int i = t; i < CI*32; i += 256) {
        int ch = i >> 5, p = i & 31;
        s_in[ch][p] = inp[(n*CI + ch)*HW + p0 + p];
    }
    for (int i = t; i < CC*32; i += 256) {
        int ch = i >> 5, p = i & 31;
        s_h[ch][p] = h[(n*CC + ch)*HW + p0 + p];
    }
    __syncthreads();

    const int c = t, g = c >> 5, cg = c & 31;
    float acc[32];
    #pragma unroll
    for (int p = 0; p < 32; p++) acc[p] = 0.f;

    const float4* wx4 = reinterpret_cast<const float4*>(Wx + c*CI);
    for (int ci4 = 0; ci4 < CI/4; ci4++) {
        float4 w = wx4[ci4];
        int cb = ci4 * 4;
        #pragma unroll
        for (int p = 0; p < 32; p++)
            acc[p] += w.x*s_in[cb][p] + w.y*s_in[cb+1][p]
                    + w.z*s_in[cb+2][p] + w.w*s_in[cb+3][p];
    }
    const float4* wg4 = reinterpret_cast<const float4*>(Wxg + c*CC);
    for (int ci4 = 0; ci4 < CC/4; ci4++) {
        float4 w = wg4[ci4];
        int cb = ci4 * 4;
        #pragma unroll
        for (int p = 0; p < 32; p++)
            acc[p] += w.x*s_h[cb][p] + w.y*s_h[cb+1][p]
                    + w.z*s_h[cb+2][p] + w.w*s_h[cb+3][p];
    }
    float* xh_x = g_xh + ((size_t)(n*C2 + g*CPG + cg))*HW + p0;
    float* xh_h = g_xh + ((size_t)(n*C2 + g*CPG + CG + cg))*HW + p0;
    #pragma unroll
    for (int p = 0; p < 32; p++) {
        xh_x[p] = acc[p];
        xh_h[p] = s_h[c][p];
    }
}

// ---------------------------------------------------------------------------
// Direct tiled grouped 9x9 conv body.
// Block: 256 threads = 16 columns x 16 rows, each thread covers 3 y-positions
// (y, y+16, y+32) for 8 output channels -> 24 accumulators.
// Input tile in smem: 2 channels x 56 rows x 24 cols (row stride 48 ->
// conflict-free for the 2-rows-per-warp access pattern).
// ---------------------------------------------------------------------------
__device__ __forceinline__ void conv9_body(
    const float* __restrict__ in_ptr,   // group input base [64][HW]
    const float* __restrict__ wt,       // weight base for oc0: [8][64][81]
    float* __restrict__ outp,           // output base for oc0: [8][OUTH*OUTW]
    int tx0, int OUTH, int OUTW, int PAD)
{
    __shared__ float s_in[2][56][48];
    __shared__ float s_w [8][2][81];
    const int t  = threadIdx.x;
    const int x  = t & 15;
    const int ty = t >> 4;

    float acc[3][8];
    #pragma unroll
    for (int j = 0; j < 3; j++)
        #pragma unroll
        for (int oc = 0; oc < 8; oc++) acc[j][oc] = 0.f;

    for (int ci0 = 0; ci0 < CPG; ci0 += 2) {
        __syncthreads();
        // input tile (zero-padded / bounds-guarded)
        for (int i = t; i < 2*56*24; i += 256) {
            int ci  = i / (56*24);
            int rem = i - ci*(56*24);
            int r   = rem / 24;
            int cc  = rem - r*24;
            int gy  = r - PAD;
            int gx  = tx0 + cc - PAD;
            float val = 0.f;
            if (gy >= 0 && gy < HH && gx >= 0 && gx < WW)
                val = in_ptr[(ci0 + ci)*HW + gy*WW + gx];
            s_in[ci][r][cc] = val;
        }
        // weights
        for (int i = t; i < 8*2*81; i += 256) {
            int oc  = i / 162;
            int rem = i - oc*162;
            int ci  = rem / 81;
            int kk  = rem - ci*81;
            s_w[oc][ci][kk] = wt[oc*(CPG*81) + (ci0 + ci)*81 + kk];
        }
        __syncthreads();

        #pragma unroll
        for (int ci = 0; ci < 2; ci++) {
            for (int ky = 0; ky < 9; ky++) {
                #pragma unroll
                for (int kx = 0; kx < 9; kx++) {
                    float v0 = s_in[ci][ty      + ky][x + kx];
                    float v1 = s_in[ci][ty + 16 + ky][x + kx];
                    float v2 = s_in[ci][ty + 32 + ky][x + kx];
                    #pragma unroll
                    for (int oc = 0; oc < 8; oc++) {
                        float w = s_w[oc][ci][ky*9 + kx];
                        acc[0][oc] = fmaf(w, v0, acc[0][oc]);
                        acc[1][oc] = fmaf(w, v1, acc[1][oc]);
                        acc[2][oc] = fmaf(w, v2, acc[2][oc]);
                    }
                }
            }
        }
    }

    const int ox = tx0 + x;
    if (ox < OUTW) {
        #pragma unroll
        for (int j = 0; j < 3; j++) {
            int oy = ty + 16*j;
            if (oy < OUTH) {
                #pragma unroll
                for (int oc = 0; oc < 8; oc++)
                    outp[oc*OUTH*OUTW + oy*OUTW + ox] = acc[j][oc];
            }
        }
    }
}

// q conv: SAME, grid (3, 4, 32)
__global__ __launch_bounds__(256) void conv_q_kernel(const float* __restrict__ Wq)
{
    int n = blockIdx.z >> 3, g = blockIdx.z & 7;
    int oc0 = blockIdx.y * 8;
    conv9_body(g_xh + ((size_t)(n*C2 + g*CPG))*HW,
               Wq   + ((size_t)(g*CG + oc0))*(CPG*81),
               g_q  + ((size_t)(n*CC + g*CG + oc0))*HW,
               blockIdx.x*16, HH, WW, 4);
}

// k & v convs: VALID, grid (3, 8, 32); blockIdx.y<4 -> k, else v
__global__ __launch_bounds__(256) void conv_kv_kernel(
    const float* __restrict__ Wk, const float* __restrict__ Wv)
{
    int n = blockIdx.z >> 3, g = blockIdx.z & 7;
    int sel = blockIdx.y >> 2;
    int oc0 = (blockIdx.y & 3) * 8;
    const float* W = sel ? Wv : Wk;
    float* out     = sel ? g_v : g_k;
    conv9_body(g_xh + ((size_t)(n*C2 + g*CPG))*HW,
               W    + ((size_t)(g*CG + oc0))*(CPG*81),
               out  + ((size_t)(n*CC + g*CG + oc0))*DD,
               blockIdx.x*16, HD, WD, 0);
}

// 4 gate convs (pre-activation): SAME, grid (3, 16, 32); blockIdx.y>>2 = gate
__global__ __launch_bounds__(256) void conv_gate_kernel(
    const float* __restrict__ W0, const float* __restrict__ W1,
    const float* __restrict__ W2, const float* __restrict__ W3)
{
    int n = blockIdx.z >> 3, g = blockIdx.z & 7;
    int gate = blockIdx.y >> 2;
    int oc0  = (blockIdx.y & 3) * 8;
    const float* W = (gate == 0) ? W0 : (gate == 1) ? W1 : (gate == 2) ? W2 : W3;
    conv9_body(g_xh   + ((size_t)(n*C2 + g*CPG))*HW,
               W      + ((size_t)(g*CG + oc0))*(CPG*81),
               g_gate + (size_t)gate*STRIDE_GATE + ((size_t)(n*CC + g*CG + oc0))*HW,
               blockIdx.x*16, HH, WW, 4);
}

// ---------------------------------------------------------------------------
// Kernel 3: attention. grid (288, 32), block 256 = 8 warps = 8 query rows.
// Each lane owns 50 of the 1600 key positions (d = lane + 32*j), scores in
// registers; k/v staged through a 32x320 smem chunk (5 chunks).
// ---------------------------------------------------------------------------
__global__ __launch_bounds__(256) void attn_kernel(const float* __restrict__ tau)
{
    __shared__ float s_kv[CG][320];
    __shared__ float s_q [8][CG];
    const int ngi = blockIdx.y;
    const int n = ngi >> 3, g = ngi & 7;
    const int r0 = blockIdx.x * 8;
    const int t = threadIdx.x, warp = t >> 5, lane = t & 31;

    for (int i = t; i < 8*CG; i += 256) {
        int r = i >> 5, c = i & 31;
        s_q[r][c] = g_q[((size_t)(n*CC + g*CG + c))*HW + r0 + r];
    }

    float sc[50];
    #pragma unroll
    for (int ch = 0; ch < 5; ch++) {
        __syncthreads();
        for (int i = t; i < CG*320; i += 256) {
            int c = i / 320, dd = i - c*320;
            s_kv[c][dd] = g_k[((size_t)(n*CC + g*CG + c))*DD + ch*320 + dd];
        }
        __syncthreads();
        float accd[10];
        #pragma unroll
        for (int j = 0; j < 10; j++) accd[j] = 0.f;
        for (int c = 0; c < CG; c++) {
            float qv = s_q[warp][c];
            #pragma unroll
            for (int j = 0; j < 10; j++)
                accd[j] = fmaf(qv, s_kv[c][lane + 32*j], accd[j]);
        }
        #pragma unroll
        for (int j = 0; j < 10; j++) sc[ch*10 + j] = accd[j];
    }

    const float tg = tau[g];
    float m = -1e30f;
    #pragma unroll
    for (int j = 0; j < 50; j++) { sc[j] *= tg; m = fmaxf(m, sc[j]); }
    #pragma unroll
    for (int o = 16; o > 0; o >>= 1)
        m = fmaxf(m, __shfl_xor_sync(0xffffffffu, m, o));
    float s = 0.f;
    #pragma unroll
    for (int j = 0; j < 50; j++) { sc[j] = __expf(sc[j] - m); s += sc[j]; }
    #pragma unroll
    for (int o = 16; o > 0; o >>= 1)
        s += __shfl_xor_sync(0xffffffffu, s, o);
    const float inv = 1.f / s;
    #pragma unroll
    for (int j = 0; j < 50; j++) sc[j] *= inv;

    float acco[CG];
    #pragma unroll
    for (int c = 0; c < CG; c++) acco[c] = 0.f;
    #pragma unroll
    for (int ch = 0; ch < 5; ch++) {
        __syncthreads();
        for (int i = t; i < CG*320; i += 256) {
            int c = i / 320, dd = i - c*320;
            s_kv[c][dd] = g_v[((size_t)(n*CC + g*CG + c))*DD + ch*320 + dd];
        }
        __syncthreads();
        #pragma unroll
        for (int j = 0; j < 10; j++) {
            float pv = sc[ch*10 + j];
            #pragma unroll
            for (int c = 0; c < CG; c++)
                acco[c] = fmaf(pv, s_kv[c][lane + 32*j], acco[c]);
        }
    }

    float myout = 0.f;
    #pragma unroll
    for (int c = 0; c < CG; c++) {
        float v = acco[c];
        #pragma unroll
        for (int o = 16; o > 0; o >>= 1)
            v += __shfl_xor_sync(0xffffffffu, v, o);
        if (lane == c) myout = v;
    }
    g_a[((size_t)(n*CC + g*CG + lane))*HW + r0 + warp] = myout;
}

// ---------------------------------------------------------------------------
// Kernel 4: grouped 1x1 Wa*a + gate pre-activations + bias -> LSTM update.
// grid (288, 4), block 256 (thread = out channel), 8 spatial positions/block.
// ---------------------------------------------------------------------------
__device__ __forceinline__ float sigmoidf_(float x) { return 1.f / (1.f + __expf(-x)); }

__global__ __launch_bounds__(256) void lstm_kernel(
    const float* __restrict__ Wa0, const float* __restrict__ Wa1,
    const float* __restrict__ Wa2, const float* __restrict__ Wa3,
    const float* __restrict__ b0,  const float* __restrict__ b1,
    const float* __restrict__ b2,  const float* __restrict__ b3,
    const float* __restrict__ c_prev, float* __restrict__ out)
{
    __shared__ float s_a[CC][8];
    const int n  = blockIdx.y;
    const int p0 = blockIdx.x * 8;
    const int t  = threadIdx.x;

    for (int i = t; i < CC*8; i += 256) {
        int ch = i >> 3, p = i & 7;
        s_a[ch][p] = g_a[((size_t)(n*CC + ch))*HW + p0 + p];
    }
    __syncthreads();

    const int c = t, g = c >> 5;
    float a0[8], a1[8], a2[8], a3[8];
    #pragma unroll
    for (int p = 0; p < 8; p++) { a0[p] = a1[p] = a2[p] = a3[p] = 0.f; }

    const float* wa0 = Wa0 + c*CG;
    const float* wa1 = Wa1 + c*CG;
    const float* wa2 = Wa2 + c*CG;
    const float* wa3 = Wa3 + c*CG;
    for (int cg = 0; cg < CG; cg++) {
        float w0 = wa0[cg], w1 = wa1[cg], w2 = wa2[cg], w3 = wa3[cg];
        const float* ar = s_a[g*CG + cg];
        #pragma unroll
        for (int p = 0; p < 8; p++) {
            float av = ar[p];
            a0[p] = fmaf(w0, av, a0[p]);
            a1[p] = fmaf(w1, av, a1[p]);
            a2[p] = fmaf(w2, av, a2[p]);
            a3[p] = fmaf(w3, av, a3[p]);
        }
    }

    const float bi = b0[c], bf = b1[c], bg = b2[c], bo = b3[c];
    const int idx0 = (n*CC + c)*HW + p0;
    #pragma unroll
    for (int p = 0; p < 8; p++) {
        int idx = idx0 + p;
        float gi = sigmoidf_(a0[p] + g_gate[                 idx] + bi);
        float gf = sigmoidf_(a1[p] + g_gate[  STRIDE_GATE  + idx] + bf);
        float gg = tanhf    (a2[p] + g_gate[2*STRIDE_GATE  + idx] + bg);
        float go = sigmoidf_(a3[p] + g_gate[3*STRIDE_GATE  + idx] + bo);
        float cn = gf * c_prev[idx] + gi * gg;
        out[idx] = go * tanhf(cn);
    }
}

// ---------------------------------------------------------------------------
extern "C" void kernel_launch(void* const* d_in, const int* in_sizes, int n_in,
                              void* d_out, int out_size)
{
    const float* inp    = (const float*)d_in[0];
    const float* h_prev = (const float*)d_in[1];
    const float* c_prev = (const float*)d_in[2];
    const float* Wx     = (const float*)d_in[3];
    const float* Wxg    = (const float*)d_in[4];
    const float* tau    = (const float*)d_in[5];
    const float* Wq     = (const float*)d_in[6];
    const float* Wk     = (const float*)d_in[7];
    const float* Wv     = (const float*)d_in[8];
    const float* Wa_i   = (const float*)d_in[9];
    const float* Wxh_i  = (const float*)d_in[10];
    const float* b_i    = (const float*)d_in[11];
    const float* Wa_f   = (const float*)d_in[12];
    const float* Wxh_f  = (const float*)d_in[13];
    const float* b_f    = (const float*)d_in[14];
    const float* Wa_g   = (const float*)d_in[15];
    const float* Wxh_g  = (const float*)d_in[16];
    const float* b_g    = (const float*)d_in[17];
    const float* Wa_o   = (const float*)d_in[18];
    const float* Wxh_o  = (const float*)d_in[19];
    const float* b_o    = (const float*)d_in[20];
    float* out = (float*)d_out;

    proj_kernel     <<<dim3(HW/32, NB), 256>>>(inp, h_prev, Wx, Wxg);
    conv_q_kernel   <<<dim3(3, 4, NB*GG), 256>>>(Wq);
    conv_kv_kernel  <<<dim3(3, 8, NB*GG), 256>>>(Wk, Wv);
    conv_gate_kernel<<<dim3(3, 16, NB*GG), 256>>>(Wxh_i, Wxh_f, Wxh_g, Wxh_o);
    attn_kernel     <<<dim3(HW/8, NB*GG), 256>>>(tau);
    lstm_kernel     <<<dim3(HW/8, NB), 256>>>(Wa_i, Wa_f, Wa_g, Wa_o,
                                              b_i, b_f, b_g, b_o, c_prev, out);
}